// round 13
// baseline (speedup 1.0000x reference)
#include <cuda_runtime.h>

// CRF Viterbi decode: B=128, S=512, T=64.
// One CTA per batch, 128 threads. Warp w owns tags 16w..16w+15;
// lanes 0-15 = predecessor seg [0,32), lanes 16-31 = seg [32,64).
// ONE __syncthreads per step; cross-segment combine via __shfl_xor(16).
// feats staged through a double-buffered SMEM ring (8 steps/chunk,
// coalesced LDG.128) so the per-step feat access is an LDS, not a
// dependent DRAM load (which was ~700 cyc of exposed stall per step).
// Bit-exact with reference: v = (f + trans[i][j]) + part[i];
// first-occurrence argmax (fmax value chains, pred-select indices,
// ascending strict-> combines, seg0 wins ties). Output float32.

#define SS 512
#define TT 64
#define START_TAG 62
#define STOP_TAG 63
#define NTHR 128

typedef unsigned long long ull;

__device__ __forceinline__ ull addx2(ull a, ull b) {
    ull r;
    asm("add.rn.f32x2 %0, %1, %2;" : "=l"(r) : "l"(a), "l"(b));
    return r;
}
__device__ __forceinline__ ull packx2(float lo, float hi) {
    ull r;
    asm("mov.b64 %0, {%1, %2};" : "=l"(r) : "f"(lo), "f"(hi));
    return r;
}
__device__ __forceinline__ void unpackx2(ull v, float& lo, float& hi) {
    asm("mov.b64 {%0, %1}, %2;" : "=f"(lo), "=f"(hi) : "l"(v));
}

// argmax chain over 4 packed pairs (8 candidates), seeded with element 0.
// Indices BASE..BASE+7; strict > keeps earliest on ties.
#define CHAIN8(CVAL, CIDX, VV, BASE) do {                                    \
    float lo_, hi_;                                                          \
    unpackx2((VV)[0], lo_, hi_);                                             \
    CVAL = lo_; CIDX = (BASE);                                               \
    CIDX = (hi_ > CVAL) ? (BASE) + 1 : CIDX;  CVAL = fmaxf(CVAL, hi_);       \
    _Pragma("unroll")                                                        \
    for (int q_ = 1; q_ < 4; ++q_) {                                         \
        unpackx2((VV)[q_], lo_, hi_);                                        \
        CIDX = (lo_ > CVAL) ? (BASE) + 2*q_     : CIDX;                      \
        CVAL = fmaxf(CVAL, lo_);                                             \
        CIDX = (hi_ > CVAL) ? (BASE) + 2*q_ + 1 : CIDX;                      \
        CVAL = fmaxf(CVAL, hi_);                                             \
    }                                                                        \
} while (0)

__global__ __launch_bounds__(NTHR, 1)
void crf_viterbi_sq(const float* __restrict__ feats,
                    const float* __restrict__ trans,
                    const unsigned* __restrict__ candA,
                    const unsigned* __restrict__ candB,
                    float* __restrict__ out)
{
    __shared__ __align__(16) float part[2][TT];
    __shared__ __align__(16) float fq[2][8][TT];   // feats ring: 2 chunks x 8 steps
    __shared__ float lastp[TT];
    __shared__ unsigned char bp[SS][TT];           // bp[t][j], t>=1, UNMASKED
    __shared__ int s_len, s_ptr0, s_clsA, s_clsB;

    const int tid  = threadIdx.x;
    const int b    = blockIdx.x;
    const int warp = tid >> 5;
    const int lane = tid & 31;
    const int tag  = (warp << 4) | (lane & 15);
    const int seg  = lane >> 4;          // 0 or 1
    const int i0   = seg << 5;           // predecessor range [i0, i0+32)
    const int frow = tid >> 4;           // staging row 0..7
    const int fcol = tid & 15;           // staging float4 column 0..15

    float* o = out + b * SS;

    // ---- transitions rows i0..i0+31 of column `tag`, packed in pairs
    ull trp[16];
#pragma unroll
    for (int u = 0; u < 16; ++u)
        trp[u] = packx2(trans[(i0 + 2*u) * TT + tag],
                        trans[(i0 + 2*u + 1) * TT + tag]);

    // ---- identify mask buffer + encoding by content ----------------------
    // bit0: words in {0,1} -> i32; bit1: {0,0x3F800000} -> f32;
    // bit2: bytes in {0,1} -> u8;  bit3: halves in {0,0x3F80} -> bf16
    if (tid == 0) { s_len = 0; s_clsA = 0xF; s_clsB = 0xF; }
    __syncthreads();
    {
        int fa = 0xF, fbc = 0xF;
        for (int s = tid; s < 512; s += NTHR) {
            unsigned w = candA[s];
            if (w > 1u) fa &= ~1;
            if (w != 0u && w != 0x3F800000u) fa &= ~2;
            if (w & 0xFEFEFEFEu) fa &= ~4;
            { unsigned hi = w >> 16, lo = w & 0xFFFFu;
              if (!((hi==0u||hi==0x3F80u) && (lo==0u||lo==0x3F80u))) fa &= ~8; }
            w = candB[s];
            if (w > 1u) fbc &= ~1;
            if (w != 0u && w != 0x3F800000u) fbc &= ~2;
            if (w & 0xFEFEFEFEu) fbc &= ~4;
            { unsigned hi = w >> 16, lo = w & 0xFFFFu;
              if (!((hi==0u||hi==0x3F80u) && (lo==0u||lo==0x3F80u))) fbc &= ~8; }
        }
        atomicAnd(&s_clsA, fa);
        atomicAnd(&s_clsB, fbc);
    }
    __syncthreads();
    const unsigned* maskw = s_clsA ? candA : candB;
    const int cls = s_clsA ? s_clsA : (s_clsB ? s_clsB : 1);

    // ---- sequence length = nonzero count in mask row b --------------------
    {
        int lsum = 0;
        if (cls & 3) {
            const unsigned* m = maskw + b * SS;
            for (int s = tid; s < SS; s += NTHR) lsum += (m[s] != 0u);
        } else if (cls & 4) {
            const unsigned char* m = (const unsigned char*)maskw + b * SS;
            for (int s = tid; s < SS; s += NTHR) lsum += (m[s] != 0);
        } else {
            const unsigned short* m = (const unsigned short*)maskw + b * SS;
            for (int s = tid; s < SS; s += NTHR) lsum += (m[s] != 0);
        }
        atomicAdd(&s_len, lsum);
    }

    const float* fb = feats + b * SS * TT;

    // ---- stage feats chunks 0 (t=0..7) and 1 (t=8..15) ---------------------
    {
        ((float4*)&fq[0][frow][0])[fcol] =
            ((const float4*)(fb + frow * TT))[fcol];
        ((float4*)&fq[1][frow][0])[fcol] =
            ((const float4*)(fb + (8 + frow) * TT))[fcol];
    }

    // ---- part0 = feats[b,0,:] + transitions[START_TAG,:] ------------------
    if (seg == 1) {                        // START row 62 = seg1, pair 15 lo
        float t62, t63;
        unpackx2(trp[15], t62, t63);
        float p0v = fb[tag] + t62;
        part[0][tag] = p0v;
        lastp[tag]   = p0v;                // correct when last_pos == 0
    }
    __syncthreads();
    int len = s_len;
    if (len < 1)  len = 1;
    if (len > SS) len = SS;
    const int last_pos = len - 1;

    // ---- ftr (packed) for t = 1 from the staged ring ------------------------
    ull ftr[16];
    {
        float f1 = fq[0][1][tag];
        ull fp = packx2(f1, f1);
#pragma unroll
        for (int u = 0; u < 16; ++u) ftr[u] = addx2(fp, trp[u]);
    }

    // ---- forward recurrence: ONE barrier per step ---------------------------
    int buf = 0;
#pragma unroll 1
    for (int t = 1; t < SS; ++t) {
        // every 8th step: stage the next chunk (coalesced LDG.128 -> STS.128);
        // consumed >= 6 barriers later, so DRAM latency is fully amortized.
        if ((t & 7) == 0) {
            int c = (t >> 3) + 1;
            if (c < SS / 8) {
                ((float4*)&fq[c & 1][frow][0])[fcol] =
                    ((const float4*)(fb + (c * 8 + frow) * TT))[fcol];
            }
        }

        // packed partition pairs for this segment (LDS.128)
        ull pvp[16];
        {
            const longlong2* p2 = (const longlong2*)(&part[buf][i0]);
#pragma unroll
            for (int q = 0; q < 8; ++q) {
                longlong2 w = p2[q];
                pvp[2*q]   = (ull)w.x;
                pvp[2*q+1] = (ull)w.y;
            }
        }

        // packed candidate values: v = ftr + pv (exact (f+tr)+p association)
        ull vv[16];
#pragma unroll
        for (int q = 0; q < 16; ++q) vv[q] = addx2(ftr[q], pvp[q]);

        float c0, c1, c2, c3; int d0, d1, d2, d3;
        CHAIN8(c0, d0, vv + 0,  0);
        CHAIN8(c1, d1, vv + 4,  8);
        CHAIN8(c2, d2, vv + 8,  16);
        CHAIN8(c3, d3, vv + 12, 24);

        // ascending combine; strict > keeps the earliest index on ties
        if (c1 > c0) { c0 = c1; d0 = d1; }
        if (c3 > c2) { c2 = c3; d2 = d3; }
        if (c2 > c0) { c0 = c2; d0 = d2; }
        float bg = c0;
        int   ag = i0 + d0;

        // cross-segment combine inside the warp (lanes l <-> l^16)
        float bo = __shfl_xor_sync(0xffffffffu, bg, 16);
        int   ao = __shfl_xor_sync(0xffffffffu, ag, 16);

        if (seg == 0) {
            float best = bg;  int arg = ag;      // seg0 wins ties
            if (bo > best) { best = bo; arg = ao; }
            part[buf ^ 1][tag] = best;
            bp[t][tag] = (unsigned char)arg;     // unmasked; masked in backtrack
            if (t == last_pos) lastp[tag] = best;
        }

        // build packed ftr for step t+1 BEFORE the barrier (f from SMEM ring)
        if (t + 1 < SS) {
            int tn = t + 1;
            float f = fq[(tn >> 3) & 1][tn & 7][tag];
            ull fp = packx2(f, f);
#pragma unroll
            for (int u = 0; u < 16; ++u) ftr[u] = addx2(fp, trp[u]);
        }

        buf ^= 1;
        __syncthreads();
    }

    // ---- pointer0 = argmax_i( lastp[i] + trans[i][STOP_TAG] ) --------------
    {
        ull vv[16];
        const longlong2* p2 = (const longlong2*)(&lastp[i0]);
#pragma unroll
        for (int q = 0; q < 8; ++q) {
            longlong2 w = p2[q];
            vv[2*q]   = addx2(trp[2*q],   (ull)w.x);
            vv[2*q+1] = addx2(trp[2*q+1], (ull)w.y);
        }
        float c0, c1, c2, c3; int d0, d1, d2, d3;
        CHAIN8(c0, d0, vv + 0,  0);
        CHAIN8(c1, d1, vv + 4,  8);
        CHAIN8(c2, d2, vv + 8,  16);
        CHAIN8(c3, d3, vv + 12, 24);
        if (c1 > c0) { c0 = c1; d0 = d1; }
        if (c3 > c2) { c2 = c3; d2 = d3; }
        if (c2 > c0) { c0 = c2; d0 = d2; }
        float bg = c0;
        int   ag = i0 + d0;

        // only threads with tag == STOP_TAG hold trans[i][STOP_TAG]; the shfl
        // pairs lanes 15/31 of warp 3, both of which have tag 63.
        float bo = __shfl_xor_sync(0xffffffffu, bg, 16);
        int   ao = __shfl_xor_sync(0xffffffffu, ag, 16);
        if (seg == 0 && tag == STOP_TAG) {
            int arg = ag;
            if (bo > bg) arg = ao;
            s_ptr0 = arg;
        }
        __syncthreads();
    }

    // ---- backtrack, float output; masking applied here -----------------------
    // Reference: decode slot SS-1 holds pointer0; for k > last_pos the masked
    // bp rows were 0 -> pointer becomes 0; at k == last_pos pointer resets to
    // p0; below that, normal chase.
    if (tid == 0) {
        const int p0 = s_ptr0;
        o[SS - 1] = (float)p0;
        int ptr = p0;
        for (int k = SS - 2; k >= 0; --k) {
            if (k > last_pos)       ptr = 0;
            else if (k == last_pos) ptr = p0;
            else                    ptr = (int)bp[k + 1][ptr];
            o[k] = (float)ptr;
        }
    }
}

extern "C" void kernel_launch(void* const* d_in, const int* in_sizes, int n_in,
                              void* d_out, int out_size) {
    // feats = largest buffer, transitions = smallest; the two leftovers are
    // {mask, tags}, disambiguated by content inside the kernel.
    int fi = 0, ti = 0;
    for (int i = 1; i < n_in; ++i) {
        if (in_sizes[i] > in_sizes[fi]) fi = i;
        if (in_sizes[i] < in_sizes[ti]) ti = i;
    }
    int cA = -1, cB = -1;
    for (int i = 0; i < n_in; ++i) {
        if (i == fi || i == ti) continue;
        if (cA < 0) cA = i; else if (cB < 0) cB = i;
    }
    if (cA < 0) cA = ti;
    if (cB < 0) cB = cA;

    const int nbatch = out_size / SS;          // 128
    crf_viterbi_sq<<<nbatch, NTHR>>>((const float*)d_in[fi],
                                     (const float*)d_in[ti],
                                     (const unsigned*)d_in[cA],
                                     (const unsigned*)d_in[cB],
                                     (float*)d_out);
}

// round 14
// speedup vs baseline: 1.0944x; 1.0944x over previous
#include <cuda_runtime.h>

// CRF Viterbi decode: B=128, S=512, T=64.
// One CTA per batch, 128 threads. Warp w owns tags 16w..16w+15;
// lanes 0-15 = predecessor seg [0,32), lanes 16-31 = seg [32,64).
// ONE __syncthreads per step; cross-segment combine via __shfl_xor(16).
// R12 core (packed add.rn.f32x2, chains seeded with candidate 0, unmasked
// bp) + 2x-unrolled forward loop (static buffers, clamped prefetch index)
// + pointer-doubling backtrack (hop2 table, 256 dependent loads vs 511).
// Bit-exact with reference: v = (f + trans[i][j]) + part[i];
// first-occurrence argmax (fmax value chains, pred-select indices,
// ascending strict-> combines, seg0 wins ties). Output float32.

#define SS 512
#define TT 64
#define START_TAG 62
#define STOP_TAG 63
#define NTHR 128

typedef unsigned long long ull;

__device__ __forceinline__ ull addx2(ull a, ull b) {
    ull r;
    asm("add.rn.f32x2 %0, %1, %2;" : "=l"(r) : "l"(a), "l"(b));
    return r;
}
__device__ __forceinline__ ull packx2(float lo, float hi) {
    ull r;
    asm("mov.b64 %0, {%1, %2};" : "=l"(r) : "f"(lo), "f"(hi));
    return r;
}
__device__ __forceinline__ void unpackx2(ull v, float& lo, float& hi) {
    asm("mov.b64 {%0, %1}, %2;" : "=f"(lo), "=f"(hi) : "l"(v));
}

// argmax chain over 4 packed pairs (8 candidates), seeded with element 0.
// Indices BASE..BASE+7; strict > keeps earliest on ties.
#define CHAIN8(CVAL, CIDX, VV, BASE) do {                                    \
    float lo_, hi_;                                                          \
    unpackx2((VV)[0], lo_, hi_);                                             \
    CVAL = lo_; CIDX = (BASE);                                               \
    CIDX = (hi_ > CVAL) ? (BASE) + 1 : CIDX;  CVAL = fmaxf(CVAL, hi_);       \
    _Pragma("unroll")                                                        \
    for (int q_ = 1; q_ < 4; ++q_) {                                         \
        unpackx2((VV)[q_], lo_, hi_);                                        \
        CIDX = (lo_ > CVAL) ? (BASE) + 2*q_     : CIDX;                      \
        CVAL = fmaxf(CVAL, lo_);                                             \
        CIDX = (hi_ > CVAL) ? (BASE) + 2*q_ + 1 : CIDX;                      \
        CVAL = fmaxf(CVAL, hi_);                                             \
    }                                                                        \
} while (0)

// One Viterbi step T: consumes prebuilt ftr (for step T), reads PIN[64],
// writes POUT[tag] / bp[T] / lastp; then builds ftr for T+1 and prefetches
// the T+2 feat row (clamped index, no branch). Ends with __syncthreads.
#define STEP(T, PIN, POUT) do {                                              \
    ull pvp[16];                                                             \
    {                                                                        \
        const longlong2* p2_ = (const longlong2*)(&(PIN)[i0]);               \
        _Pragma("unroll")                                                    \
        for (int q_ = 0; q_ < 8; ++q_) {                                     \
            longlong2 w_ = p2_[q_];                                          \
            pvp[2*q_]   = (ull)w_.x;                                         \
            pvp[2*q_+1] = (ull)w_.y;                                         \
        }                                                                    \
    }                                                                        \
    ull vv[16];                                                              \
    _Pragma("unroll")                                                        \
    for (int q_ = 0; q_ < 16; ++q_) vv[q_] = addx2(ftr[q_], pvp[q_]);        \
    float c0, c1, c2, c3; int d0, d1, d2, d3;                                \
    CHAIN8(c0, d0, vv + 0,  0);                                              \
    CHAIN8(c1, d1, vv + 4,  8);                                              \
    CHAIN8(c2, d2, vv + 8,  16);                                             \
    CHAIN8(c3, d3, vv + 12, 24);                                             \
    if (c1 > c0) { c0 = c1; d0 = d1; }                                       \
    if (c3 > c2) { c2 = c3; d2 = d3; }                                       \
    if (c2 > c0) { c0 = c2; d0 = d2; }                                       \
    float bg_ = c0;                                                          \
    int   ag_ = i0 + d0;                                                     \
    float bo_ = __shfl_xor_sync(0xffffffffu, bg_, 16);                       \
    int   ao_ = __shfl_xor_sync(0xffffffffu, ag_, 16);                       \
    if (seg == 0) {                                                          \
        float best_ = bg_;  int arg_ = ag_;                                  \
        if (bo_ > best_) { best_ = bo_; arg_ = ao_; }                        \
        (POUT)[tag] = best_;                                                 \
        bp[(T)][tag] = (unsigned char)arg_;                                  \
        if ((T) == last_pos) lastp[tag] = best_;                             \
    }                                                                        \
    {                                                                        \
        float f_ = fnext;                                                    \
        int tn_ = ((T) + 2 < SS) ? (T) + 2 : SS - 1;                         \
        fnext = fb[tn_ * TT + tag];                                          \
        ull fp_ = packx2(f_, f_);                                            \
        _Pragma("unroll")                                                    \
        for (int u_ = 0; u_ < 16; ++u_) ftr[u_] = addx2(fp_, trp[u_]);       \
    }                                                                        \
    __syncthreads();                                                         \
} while (0)

__global__ __launch_bounds__(NTHR, 1)
void crf_viterbi_v14(const float* __restrict__ feats,
                     const float* __restrict__ trans,
                     const unsigned* __restrict__ candA,
                     const unsigned* __restrict__ candB,
                     float* __restrict__ out)
{
    __shared__ __align__(16) float part[2][TT];
    __shared__ float lastp[TT];
    __shared__ unsigned char bp[SS][TT];   // bp[t][j], t>=1, UNMASKED
    __shared__ int sptr[SS];               // chased pointers (even offsets)
    __shared__ int s_len, s_ptr0, s_clsA, s_clsB;
    extern __shared__ unsigned char hop2[];  // [SS][TT], rows 1..510 used

    const int tid  = threadIdx.x;
    const int b    = blockIdx.x;
    const int warp = tid >> 5;
    const int lane = tid & 31;
    const int tag  = (warp << 4) | (lane & 15);
    const int seg  = lane >> 4;          // 0 or 1
    const int i0   = seg << 5;           // predecessor range [i0, i0+32)

    float* o = out + b * SS;

    // ---- transitions rows i0..i0+31 of column `tag`, packed in pairs
    ull trp[16];
#pragma unroll
    for (int u = 0; u < 16; ++u)
        trp[u] = packx2(trans[(i0 + 2*u) * TT + tag],
                        trans[(i0 + 2*u + 1) * TT + tag]);

    // ---- identify mask buffer + encoding by content ----------------------
    // bit0: words in {0,1} -> i32; bit1: {0,0x3F800000} -> f32;
    // bit2: bytes in {0,1} -> u8;  bit3: halves in {0,0x3F80} -> bf16
    if (tid == 0) { s_len = 0; s_clsA = 0xF; s_clsB = 0xF; }
    __syncthreads();
    {
        int fa = 0xF, fbc = 0xF;
        for (int s = tid; s < 512; s += NTHR) {
            unsigned w = candA[s];
            if (w > 1u) fa &= ~1;
            if (w != 0u && w != 0x3F800000u) fa &= ~2;
            if (w & 0xFEFEFEFEu) fa &= ~4;
            { unsigned hi = w >> 16, lo = w & 0xFFFFu;
              if (!((hi==0u||hi==0x3F80u) && (lo==0u||lo==0x3F80u))) fa &= ~8; }
            w = candB[s];
            if (w > 1u) fbc &= ~1;
            if (w != 0u && w != 0x3F800000u) fbc &= ~2;
            if (w & 0xFEFEFEFEu) fbc &= ~4;
            { unsigned hi = w >> 16, lo = w & 0xFFFFu;
              if (!((hi==0u||hi==0x3F80u) && (lo==0u||lo==0x3F80u))) fbc &= ~8; }
        }
        atomicAnd(&s_clsA, fa);
        atomicAnd(&s_clsB, fbc);
    }
    __syncthreads();
    const unsigned* maskw = s_clsA ? candA : candB;
    const int cls = s_clsA ? s_clsA : (s_clsB ? s_clsB : 1);

    // ---- sequence length = nonzero count in mask row b --------------------
    {
        int lsum = 0;
        if (cls & 3) {
            const unsigned* m = maskw + b * SS;
            for (int s = tid; s < SS; s += NTHR) lsum += (m[s] != 0u);
        } else if (cls & 4) {
            const unsigned char* m = (const unsigned char*)maskw + b * SS;
            for (int s = tid; s < SS; s += NTHR) lsum += (m[s] != 0);
        } else {
            const unsigned short* m = (const unsigned short*)maskw + b * SS;
            for (int s = tid; s < SS; s += NTHR) lsum += (m[s] != 0);
        }
        atomicAdd(&s_len, lsum);
    }

    // ---- part0 = feats[b,0,:] + transitions[START_TAG,:] ------------------
    const float* fb = feats + b * SS * TT;
    if (seg == 1) {                        // START row 62 = seg1, pair 15 lo
        float t62, t63;
        unpackx2(trp[15], t62, t63);
        float p0v = fb[tag] + t62;
        part[0][tag] = p0v;
        lastp[tag]   = p0v;                // correct when last_pos == 0
    }
    __syncthreads();
    int len = s_len;
    if (len < 1)  len = 1;
    if (len > SS) len = SS;
    const int last_pos = len - 1;

    // ---- ftr (packed) for t = 1, prefetch feat row t = 2 --------------------
    ull ftr[16];
    {
        float f1 = fb[TT + tag];
        ull fp = packx2(f1, f1);
#pragma unroll
        for (int u = 0; u < 16; ++u) ftr[u] = addx2(fp, trp[u]);
    }
    float fnext = fb[2 * TT + tag];

    // ---- forward recurrence: 2x unrolled, ONE barrier per step --------------
#pragma unroll 1
    for (int t = 1; t < SS - 1; t += 2) {
        STEP(t,     part[0], part[1]);
        STEP(t + 1, part[1], part[0]);
    }
    STEP(SS - 1, part[0], part[1]);        // step 511

    // ---- pointer0 = argmax_i( lastp[i] + trans[i][STOP_TAG] ) --------------
    {
        ull vv[16];
        const longlong2* p2 = (const longlong2*)(&lastp[i0]);
#pragma unroll
        for (int q = 0; q < 8; ++q) {
            longlong2 w = p2[q];
            vv[2*q]   = addx2(trp[2*q],   (ull)w.x);
            vv[2*q+1] = addx2(trp[2*q+1], (ull)w.y);
        }
        float c0, c1, c2, c3; int d0, d1, d2, d3;
        CHAIN8(c0, d0, vv + 0,  0);
        CHAIN8(c1, d1, vv + 4,  8);
        CHAIN8(c2, d2, vv + 8,  16);
        CHAIN8(c3, d3, vv + 12, 24);
        if (c1 > c0) { c0 = c1; d0 = d1; }
        if (c3 > c2) { c2 = c3; d2 = d3; }
        if (c2 > c0) { c0 = c2; d0 = d2; }
        float bg = c0;
        int   ag = i0 + d0;

        // only threads with tag == STOP_TAG hold trans[i][STOP_TAG]; the shfl
        // pairs lanes 15/31 of warp 3, both of which have tag 63.
        float bo = __shfl_xor_sync(0xffffffffu, bg, 16);
        int   ao = __shfl_xor_sync(0xffffffffu, ag, 16);
        if (seg == 0 && tag == STOP_TAG) {
            int arg = ag;
            if (bo > bg) arg = ao;
            s_ptr0 = arg;
        }
        __syncthreads();
    }

    // ---- backtrack via pointer doubling --------------------------------------
    // hop2[t][j] = bp[t][bp[t+1][j]] composes two chase steps; the serial
    // chain then needs only ceil(last_pos/2) dependent loads. Odd-offset
    // positions are recovered afterwards with independent parallel lookups.
    // Masked region handled directly (never reads bp beyond last_pos).
    for (int idx = tid; idx < (SS - 2) * TT; idx += NTHR) {
        int t = 1 + (idx >> 6);
        int j = idx & 63;
        hop2[t * TT + j] = bp[t][bp[t + 1][j]];
    }
    __syncthreads();

    if (tid == 0) {
        const int p0 = s_ptr0;
        o[SS - 1] = (float)p0;             // reference: decode[-1] = pointer0
        int m = last_pos, ptr = p0;
        sptr[m] = ptr;
        o[m] = (float)ptr;
        while (m >= 2) {
            ptr = (int)hop2[(m - 1) * TT + ptr];   // ptr_{m-2}
            m -= 2;
            sptr[m] = ptr;
            o[m] = (float)ptr;
        }
    }
    __syncthreads();

    // zeros beyond last_pos, odd-offset fixups below it
    for (int k = tid; k < SS - 1; k += NTHR) {
        if (k > last_pos) {
            o[k] = 0.0f;
        } else if (k < last_pos && ((last_pos - k) & 1)) {
            o[k] = (float)(int)bp[k + 1][sptr[k + 1]];
        }
    }
}

extern "C" void kernel_launch(void* const* d_in, const int* in_sizes, int n_in,
                              void* d_out, int out_size) {
    // feats = largest buffer, transitions = smallest; the two leftovers are
    // {mask, tags}, disambiguated by content inside the kernel.
    int fi = 0, ti = 0;
    for (int i = 1; i < n_in; ++i) {
        if (in_sizes[i] > in_sizes[fi]) fi = i;
        if (in_sizes[i] < in_sizes[ti]) ti = i;
    }
    int cA = -1, cB = -1;
    for (int i = 0; i < n_in; ++i) {
        if (i == fi || i == ti) continue;
        if (cA < 0) cA = i; else if (cB < 0) cB = i;
    }
    if (cA < 0) cA = ti;
    if (cB < 0) cB = cA;

    const int HOP_BYTES = SS * TT;             // 32 KB dynamic smem
    cudaFuncSetAttribute(crf_viterbi_v14,
                         cudaFuncAttributeMaxDynamicSharedMemorySize, HOP_BYTES);

    const int nbatch = out_size / SS;          // 128
    crf_viterbi_v14<<<nbatch, NTHR, HOP_BYTES>>>(
        (const float*)d_in[fi],
        (const float*)d_in[ti],
        (const unsigned*)d_in[cA],
        (const unsigned*)d_in[cB],
        (float*)d_out);
}

// round 15
// speedup vs baseline: 1.2961x; 1.1843x over previous
#include <cuda_runtime.h>

// CRF Viterbi decode: B=128, S=512, T=64.
// One CTA per batch, 128 threads. Warp w owns tags 16w..16w+15;
// lanes 0-15 = predecessor seg [0,32), lanes 16-31 = seg [32,64).
// ONE __syncthreads per step; cross-segment combine via __shfl_xor(16).
// R12 core (packed add.rn.f32x2, chains seeded with candidate 0, unmasked
// bp, masking in backtrack) + depth-2 feat prefetch + balanced writer
// roles (seg0 stores part; seg1 stores bp/lastp — both compute the
// identical combined result from the shfl exchange).
// Bit-exact with reference: v = (f + trans[i][j]) + part[i];
// first-occurrence argmax (fmax value chains, pred-select indices,
// ascending strict-> combines, seg0 wins ties). Output float32.

#define SS 512
#define TT 64
#define START_TAG 62
#define STOP_TAG 63
#define NTHR 128

typedef unsigned long long ull;

__device__ __forceinline__ ull addx2(ull a, ull b) {
    ull r;
    asm("add.rn.f32x2 %0, %1, %2;" : "=l"(r) : "l"(a), "l"(b));
    return r;
}
__device__ __forceinline__ ull packx2(float lo, float hi) {
    ull r;
    asm("mov.b64 %0, {%1, %2};" : "=l"(r) : "f"(lo), "f"(hi));
    return r;
}
__device__ __forceinline__ void unpackx2(ull v, float& lo, float& hi) {
    asm("mov.b64 {%0, %1}, %2;" : "=f"(lo), "=f"(hi) : "l"(v));
}

// argmax chain over 4 packed pairs (8 candidates), seeded with element 0.
// Indices BASE..BASE+7; strict > keeps earliest on ties.
#define CHAIN8(CVAL, CIDX, VV, BASE) do {                                    \
    float lo_, hi_;                                                          \
    unpackx2((VV)[0], lo_, hi_);                                             \
    CVAL = lo_; CIDX = (BASE);                                               \
    CIDX = (hi_ > CVAL) ? (BASE) + 1 : CIDX;  CVAL = fmaxf(CVAL, hi_);       \
    _Pragma("unroll")                                                        \
    for (int q_ = 1; q_ < 4; ++q_) {                                         \
        unpackx2((VV)[q_], lo_, hi_);                                        \
        CIDX = (lo_ > CVAL) ? (BASE) + 2*q_     : CIDX;                      \
        CVAL = fmaxf(CVAL, lo_);                                             \
        CIDX = (hi_ > CVAL) ? (BASE) + 2*q_ + 1 : CIDX;                      \
        CVAL = fmaxf(CVAL, hi_);                                             \
    }                                                                        \
} while (0)

__global__ __launch_bounds__(NTHR, 1)
void crf_viterbi_v15(const float* __restrict__ feats,
                     const float* __restrict__ trans,
                     const unsigned* __restrict__ candA,
                     const unsigned* __restrict__ candB,
                     float* __restrict__ out)
{
    __shared__ __align__(16) float part[2][TT];
    __shared__ float lastp[TT];
    __shared__ unsigned char bp[SS][TT];   // bp[t][j], t>=1, UNMASKED
    __shared__ int s_len, s_ptr0, s_clsA, s_clsB;

    const int tid  = threadIdx.x;
    const int b    = blockIdx.x;
    const int warp = tid >> 5;
    const int lane = tid & 31;
    const int tag  = (warp << 4) | (lane & 15);
    const int seg  = lane >> 4;          // 0 or 1
    const int i0   = seg << 5;           // predecessor range [i0, i0+32)

    float* o = out + b * SS;

    // ---- transitions rows i0..i0+31 of column `tag`, packed in pairs
    ull trp[16];
#pragma unroll
    for (int u = 0; u < 16; ++u)
        trp[u] = packx2(trans[(i0 + 2*u) * TT + tag],
                        trans[(i0 + 2*u + 1) * TT + tag]);

    // ---- identify mask buffer + encoding by content ----------------------
    // bit0: words in {0,1} -> i32; bit1: {0,0x3F800000} -> f32;
    // bit2: bytes in {0,1} -> u8;  bit3: halves in {0,0x3F80} -> bf16
    if (tid == 0) { s_len = 0; s_clsA = 0xF; s_clsB = 0xF; }
    __syncthreads();
    {
        int fa = 0xF, fbc = 0xF;
        for (int s = tid; s < 512; s += NTHR) {
            unsigned w = candA[s];
            if (w > 1u) fa &= ~1;
            if (w != 0u && w != 0x3F800000u) fa &= ~2;
            if (w & 0xFEFEFEFEu) fa &= ~4;
            { unsigned hi = w >> 16, lo = w & 0xFFFFu;
              if (!((hi==0u||hi==0x3F80u) && (lo==0u||lo==0x3F80u))) fa &= ~8; }
            w = candB[s];
            if (w > 1u) fbc &= ~1;
            if (w != 0u && w != 0x3F800000u) fbc &= ~2;
            if (w & 0xFEFEFEFEu) fbc &= ~4;
            { unsigned hi = w >> 16, lo = w & 0xFFFFu;
              if (!((hi==0u||hi==0x3F80u) && (lo==0u||lo==0x3F80u))) fbc &= ~8; }
        }
        atomicAnd(&s_clsA, fa);
        atomicAnd(&s_clsB, fbc);
    }
    __syncthreads();
    const unsigned* maskw = s_clsA ? candA : candB;
    const int cls = s_clsA ? s_clsA : (s_clsB ? s_clsB : 1);

    // ---- sequence length = nonzero count in mask row b --------------------
    {
        int lsum = 0;
        if (cls & 3) {
            const unsigned* m = maskw + b * SS;
            for (int s = tid; s < SS; s += NTHR) lsum += (m[s] != 0u);
        } else if (cls & 4) {
            const unsigned char* m = (const unsigned char*)maskw + b * SS;
            for (int s = tid; s < SS; s += NTHR) lsum += (m[s] != 0);
        } else {
            const unsigned short* m = (const unsigned short*)maskw + b * SS;
            for (int s = tid; s < SS; s += NTHR) lsum += (m[s] != 0);
        }
        atomicAdd(&s_len, lsum);
    }

    // ---- part0 = feats[b,0,:] + transitions[START_TAG,:] ------------------
    const float* fb = feats + b * SS * TT;
    if (seg == 1) {                        // START row 62 = seg1, pair 15 lo
        float t62, t63;
        unpackx2(trp[15], t62, t63);
        float p0v = fb[tag] + t62;
        part[0][tag] = p0v;
        lastp[tag]   = p0v;                // correct when last_pos == 0
    }
    __syncthreads();
    int len = s_len;
    if (len < 1)  len = 1;
    if (len > SS) len = SS;
    const int last_pos = len - 1;

    // ---- ftr (packed) for t = 1; depth-2 feat prefetch ----------------------
    ull ftr[16];
    {
        float f1 = fb[TT + tag];
        ull fp = packx2(f1, f1);
#pragma unroll
        for (int u = 0; u < 16; ++u) ftr[u] = addx2(fp, trp[u]);
    }
    float fn1 = fb[2 * TT + tag];          // f(t+1) entering t=1
    float fn2 = fb[3 * TT + tag];          // f(t+2) entering t=1

    // ---- forward recurrence: ONE barrier per step ---------------------------
    int buf = 0;
#pragma unroll 1
    for (int t = 1; t < SS; ++t) {
        // packed partition pairs for this segment (LDS.128)
        ull pvp[16];
        {
            const longlong2* p2 = (const longlong2*)(&part[buf][i0]);
#pragma unroll
            for (int q = 0; q < 8; ++q) {
                longlong2 w = p2[q];
                pvp[2*q]   = (ull)w.x;
                pvp[2*q+1] = (ull)w.y;
            }
        }

        // packed candidate values: v = ftr + pv (exact (f+tr)+p association)
        ull vv[16];
#pragma unroll
        for (int q = 0; q < 16; ++q) vv[q] = addx2(ftr[q], pvp[q]);

        float c0, c1, c2, c3; int d0, d1, d2, d3;
        CHAIN8(c0, d0, vv + 0,  0);
        CHAIN8(c1, d1, vv + 4,  8);
        CHAIN8(c2, d2, vv + 8,  16);
        CHAIN8(c3, d3, vv + 12, 24);

        // ascending combine; strict > keeps the earliest index on ties
        if (c1 > c0) { c0 = c1; d0 = d1; }
        if (c3 > c2) { c2 = c3; d2 = d3; }
        if (c2 > c0) { c0 = c2; d0 = d2; }
        float bg = c0;
        int   ag = i0 + d0;

        // cross-segment combine inside the warp (lanes l <-> l^16)
        float bo = __shfl_xor_sync(0xffffffffu, bg, 16);
        int   ao = __shfl_xor_sync(0xffffffffu, ag, 16);

        // both segments compute the identical combined result (seg0 wins ties);
        // writer roles split to balance per-lane work: seg0 -> part,
        // seg1 -> bp / lastp.
        if (seg == 0) {
            float best = bg;
            if (bo > best) best = bo;
            part[buf ^ 1][tag] = best;
        } else {
            // here bo/ao are seg0's results: adopt own only on strict >
            float best = bo;  int arg = ao;
            if (bg > bo) { best = bg; arg = ag; }
            bp[t][tag] = (unsigned char)arg;   // unmasked; masked in backtrack
            if (t == last_pos) lastp[tag] = best;
        }

        // build packed ftr for step t+1 BEFORE the barrier (depth-2 pipeline)
        {
            float f = fn1;
            fn1 = fn2;
            if (t + 3 < SS) fn2 = fb[(t + 3) * TT + tag];
            ull fp = packx2(f, f);
#pragma unroll
            for (int u = 0; u < 16; ++u) ftr[u] = addx2(fp, trp[u]);
        }

        buf ^= 1;
        __syncthreads();
    }

    // ---- pointer0 = argmax_i( lastp[i] + trans[i][STOP_TAG] ) --------------
    {
        ull vv[16];
        const longlong2* p2 = (const longlong2*)(&lastp[i0]);
#pragma unroll
        for (int q = 0; q < 8; ++q) {
            longlong2 w = p2[q];
            vv[2*q]   = addx2(trp[2*q],   (ull)w.x);
            vv[2*q+1] = addx2(trp[2*q+1], (ull)w.y);
        }
        float c0, c1, c2, c3; int d0, d1, d2, d3;
        CHAIN8(c0, d0, vv + 0,  0);
        CHAIN8(c1, d1, vv + 4,  8);
        CHAIN8(c2, d2, vv + 8,  16);
        CHAIN8(c3, d3, vv + 12, 24);
        if (c1 > c0) { c0 = c1; d0 = d1; }
        if (c3 > c2) { c2 = c3; d2 = d3; }
        if (c2 > c0) { c0 = c2; d0 = d2; }
        float bg = c0;
        int   ag = i0 + d0;

        // only threads with tag == STOP_TAG hold trans[i][STOP_TAG]; the shfl
        // pairs lanes 15/31 of warp 3, both of which have tag 63.
        float bo = __shfl_xor_sync(0xffffffffu, bg, 16);
        int   ao = __shfl_xor_sync(0xffffffffu, ag, 16);
        if (seg == 0 && tag == STOP_TAG) {
            int arg = ag;
            if (bo > bg) arg = ao;
            s_ptr0 = arg;
        }
        __syncthreads();
    }

    // ---- backtrack, float output; masking applied here -----------------------
    // Reference: decode slot SS-1 holds pointer0; for k > last_pos the masked
    // bp rows were 0 -> pointer becomes 0; at k == last_pos pointer resets to
    // p0; below that, normal chase.
    if (tid == 0) {
        const int p0 = s_ptr0;
        o[SS - 1] = (float)p0;
        int ptr = p0;
        for (int k = SS - 2; k >= 0; --k) {
            if (k > last_pos)       ptr = 0;
            else if (k == last_pos) ptr = p0;
            else                    ptr = (int)bp[k + 1][ptr];
            o[k] = (float)ptr;
        }
    }
}

extern "C" void kernel_launch(void* const* d_in, const int* in_sizes, int n_in,
                              void* d_out, int out_size) {
    // feats = largest buffer, transitions = smallest; the two leftovers are
    // {mask, tags}, disambiguated by content inside the kernel.
    int fi = 0, ti = 0;
    for (int i = 1; i < n_in; ++i) {
        if (in_sizes[i] > in_sizes[fi]) fi = i;
        if (in_sizes[i] < in_sizes[ti]) ti = i;
    }
    int cA = -1, cB = -1;
    for (int i = 0; i < n_in; ++i) {
        if (i == fi || i == ti) continue;
        if (cA < 0) cA = i; else if (cB < 0) cB = i;
    }
    if (cA < 0) cA = ti;
    if (cB < 0) cB = cA;

    const int nbatch = out_size / SS;          // 128
    crf_viterbi_v15<<<nbatch, NTHR>>>((const float*)d_in[fi],
                                      (const float*)d_in[ti],
                                      (const unsigned*)d_in[cA],
                                      (const unsigned*)d_in[cB],
                                      (float*)d_out);
}

// round 16
// speedup vs baseline: 1.3773x; 1.0627x over previous
#include <cuda_runtime.h>

// CRF Viterbi decode: B=128, S=512, T=64.
// One CTA per batch, 128 threads. Warp w owns tags 16w..16w+15;
// lanes 0-15 = predecessor seg [0,32), lanes 16-31 = seg [32,64).
// ONE __syncthreads per step; cross-segment combine via __shfl_xor(16).
// R12 core (packed add.rn.f32x2, chains seeded with candidate 0, unmasked
// bp, masking in backtrack) with value/index-split combines: the partition
// value comes from a short FMNMX tree (critical path), the argmax index
// from equality-selects off the critical path. First-occurrence ties
// preserved (ascending chunk priority, seg0 wins ties).
// Bit-exact with reference: v = (f + trans[i][j]) + part[i]. Output float32.

#define SS 512
#define TT 64
#define START_TAG 62
#define STOP_TAG 63
#define NTHR 128

typedef unsigned long long ull;

__device__ __forceinline__ ull addx2(ull a, ull b) {
    ull r;
    asm("add.rn.f32x2 %0, %1, %2;" : "=l"(r) : "l"(a), "l"(b));
    return r;
}
__device__ __forceinline__ ull packx2(float lo, float hi) {
    ull r;
    asm("mov.b64 %0, {%1, %2};" : "=l"(r) : "f"(lo), "f"(hi));
    return r;
}
__device__ __forceinline__ void unpackx2(ull v, float& lo, float& hi) {
    asm("mov.b64 {%0, %1}, %2;" : "=f"(lo), "=f"(hi) : "l"(v));
}

// argmax chain over 4 packed pairs (8 candidates), seeded with element 0.
// Indices BASE..BASE+7; strict > keeps earliest on ties.
#define CHAIN8(CVAL, CIDX, VV, BASE) do {                                    \
    float lo_, hi_;                                                          \
    unpackx2((VV)[0], lo_, hi_);                                             \
    CVAL = lo_; CIDX = (BASE);                                               \
    CIDX = (hi_ > CVAL) ? (BASE) + 1 : CIDX;  CVAL = fmaxf(CVAL, hi_);       \
    _Pragma("unroll")                                                        \
    for (int q_ = 1; q_ < 4; ++q_) {                                         \
        unpackx2((VV)[q_], lo_, hi_);                                        \
        CIDX = (lo_ > CVAL) ? (BASE) + 2*q_     : CIDX;                      \
        CVAL = fmaxf(CVAL, lo_);                                             \
        CIDX = (hi_ > CVAL) ? (BASE) + 2*q_ + 1 : CIDX;                      \
        CVAL = fmaxf(CVAL, hi_);                                             \
    }                                                                        \
} while (0)

__global__ __launch_bounds__(NTHR, 1)
void crf_viterbi_v16(const float* __restrict__ feats,
                     const float* __restrict__ trans,
                     const unsigned* __restrict__ candA,
                     const unsigned* __restrict__ candB,
                     float* __restrict__ out)
{
    __shared__ __align__(16) float part[2][TT];
    __shared__ float lastp[TT];
    __shared__ unsigned char bp[SS][TT];   // bp[t][j], t>=1, UNMASKED
    __shared__ int s_len, s_ptr0, s_clsA, s_clsB;

    const int tid  = threadIdx.x;
    const int b    = blockIdx.x;
    const int warp = tid >> 5;
    const int lane = tid & 31;
    const int tag  = (warp << 4) | (lane & 15);
    const int seg  = lane >> 4;          // 0 or 1
    const int i0   = seg << 5;           // predecessor range [i0, i0+32)

    float* o = out + b * SS;

    // ---- transitions rows i0..i0+31 of column `tag`, packed in pairs
    ull trp[16];
#pragma unroll
    for (int u = 0; u < 16; ++u)
        trp[u] = packx2(trans[(i0 + 2*u) * TT + tag],
                        trans[(i0 + 2*u + 1) * TT + tag]);

    // ---- identify mask buffer + encoding by content ----------------------
    // bit0: words in {0,1} -> i32; bit1: {0,0x3F800000} -> f32;
    // bit2: bytes in {0,1} -> u8;  bit3: halves in {0,0x3F80} -> bf16
    if (tid == 0) { s_len = 0; s_clsA = 0xF; s_clsB = 0xF; }
    __syncthreads();
    {
        int fa = 0xF, fbc = 0xF;
        for (int s = tid; s < 512; s += NTHR) {
            unsigned w = candA[s];
            if (w > 1u) fa &= ~1;
            if (w != 0u && w != 0x3F800000u) fa &= ~2;
            if (w & 0xFEFEFEFEu) fa &= ~4;
            { unsigned hi = w >> 16, lo = w & 0xFFFFu;
              if (!((hi==0u||hi==0x3F80u) && (lo==0u||lo==0x3F80u))) fa &= ~8; }
            w = candB[s];
            if (w > 1u) fbc &= ~1;
            if (w != 0u && w != 0x3F800000u) fbc &= ~2;
            if (w & 0xFEFEFEFEu) fbc &= ~4;
            { unsigned hi = w >> 16, lo = w & 0xFFFFu;
              if (!((hi==0u||hi==0x3F80u) && (lo==0u||lo==0x3F80u))) fbc &= ~8; }
        }
        atomicAnd(&s_clsA, fa);
        atomicAnd(&s_clsB, fbc);
    }
    __syncthreads();
    const unsigned* maskw = s_clsA ? candA : candB;
    const int cls = s_clsA ? s_clsA : (s_clsB ? s_clsB : 1);

    // ---- sequence length = nonzero count in mask row b --------------------
    {
        int lsum = 0;
        if (cls & 3) {
            const unsigned* m = maskw + b * SS;
            for (int s = tid; s < SS; s += NTHR) lsum += (m[s] != 0u);
        } else if (cls & 4) {
            const unsigned char* m = (const unsigned char*)maskw + b * SS;
            for (int s = tid; s < SS; s += NTHR) lsum += (m[s] != 0);
        } else {
            const unsigned short* m = (const unsigned short*)maskw + b * SS;
            for (int s = tid; s < SS; s += NTHR) lsum += (m[s] != 0);
        }
        atomicAdd(&s_len, lsum);
    }

    // ---- part0 = feats[b,0,:] + transitions[START_TAG,:] ------------------
    const float* fb = feats + b * SS * TT;
    if (seg == 1) {                        // START row 62 = seg1, pair 15 lo
        float t62, t63;
        unpackx2(trp[15], t62, t63);
        float p0v = fb[tag] + t62;
        part[0][tag] = p0v;
        lastp[tag]   = p0v;                // correct when last_pos == 0
    }
    __syncthreads();
    int len = s_len;
    if (len < 1)  len = 1;
    if (len > SS) len = SS;
    const int last_pos = len - 1;

    // ---- ftr (packed) for t = 1, prefetch feat for t = 2 -------------------
    ull ftr[16];
    {
        float f1 = fb[TT + tag];
        ull fp = packx2(f1, f1);
#pragma unroll
        for (int u = 0; u < 16; ++u) ftr[u] = addx2(fp, trp[u]);
    }
    float fnext = fb[2 * TT + tag];

    // ---- forward recurrence: ONE barrier per step ---------------------------
    int buf = 0;
#pragma unroll 1
    for (int t = 1; t < SS; ++t) {
        // packed partition pairs for this segment (LDS.128)
        ull pvp[16];
        {
            const longlong2* p2 = (const longlong2*)(&part[buf][i0]);
#pragma unroll
            for (int q = 0; q < 8; ++q) {
                longlong2 w = p2[q];
                pvp[2*q]   = (ull)w.x;
                pvp[2*q+1] = (ull)w.y;
            }
        }

        // packed candidate values: v = ftr + pv (exact (f+tr)+p association)
        ull vv[16];
#pragma unroll
        for (int q = 0; q < 16; ++q) vv[q] = addx2(ftr[q], pvp[q]);

        float c0, c1, c2, c3; int d0, d1, d2, d3;
        CHAIN8(c0, d0, vv + 0,  0);
        CHAIN8(c1, d1, vv + 4,  8);
        CHAIN8(c2, d2, vv + 8,  16);
        CHAIN8(c3, d3, vv + 12, 24);

        // value via short FMNMX tree (critical path); index via
        // equality-selects (off critical path). Ascending chunk priority
        // keeps first-occurrence ties.
        float bg = fmaxf(fmaxf(c0, c1), fmaxf(c2, c3));
        int   ag = (c0 == bg) ? d0 : (c1 == bg) ? d1 : (c2 == bg) ? d2 : d3;
        ag += i0;

        // cross-segment combine inside the warp (lanes l <-> l^16)
        float bo = __shfl_xor_sync(0xffffffffu, bg, 16);
        int   ao = __shfl_xor_sync(0xffffffffu, ag, 16);

        if (seg == 0) {
            float best = fmaxf(bg, bo);              // 4-cyc value path
            int   arg  = (bg == best) ? ag : ao;     // seg0 wins ties
            part[buf ^ 1][tag] = best;
            bp[t][tag] = (unsigned char)arg;         // unmasked; masked later
            if (t == last_pos) lastp[tag] = best;
        }

        // build packed ftr for step t+1 BEFORE the barrier
        {
            float f = fnext;
            if (t + 2 < SS) fnext = fb[(t + 2) * TT + tag];
            ull fp = packx2(f, f);
#pragma unroll
            for (int u = 0; u < 16; ++u) ftr[u] = addx2(fp, trp[u]);
        }

        buf ^= 1;
        __syncthreads();
    }

    // ---- pointer0 = argmax_i( lastp[i] + trans[i][STOP_TAG] ) --------------
    {
        ull vv[16];
        const longlong2* p2 = (const longlong2*)(&lastp[i0]);
#pragma unroll
        for (int q = 0; q < 8; ++q) {
            longlong2 w = p2[q];
            vv[2*q]   = addx2(trp[2*q],   (ull)w.x);
            vv[2*q+1] = addx2(trp[2*q+1], (ull)w.y);
        }
        float c0, c1, c2, c3; int d0, d1, d2, d3;
        CHAIN8(c0, d0, vv + 0,  0);
        CHAIN8(c1, d1, vv + 4,  8);
        CHAIN8(c2, d2, vv + 8,  16);
        CHAIN8(c3, d3, vv + 12, 24);
        float bg = fmaxf(fmaxf(c0, c1), fmaxf(c2, c3));
        int   ag = (c0 == bg) ? d0 : (c1 == bg) ? d1 : (c2 == bg) ? d2 : d3;
        ag += i0;

        // only threads with tag == STOP_TAG hold trans[i][STOP_TAG]; the shfl
        // pairs lanes 15/31 of warp 3, both of which have tag 63.
        float bo = __shfl_xor_sync(0xffffffffu, bg, 16);
        int   ao = __shfl_xor_sync(0xffffffffu, ag, 16);
        if (seg == 0 && tag == STOP_TAG) {
            float best = fmaxf(bg, bo);
            s_ptr0 = (bg == best) ? ag : ao;         // seg0 wins ties
        }
        __syncthreads();
    }

    // ---- backtrack, float output; masking applied here -----------------------
    // Reference: decode slot SS-1 holds pointer0; for k > last_pos the masked
    // bp rows were 0 -> pointer becomes 0; at k == last_pos pointer resets to
    // p0; below that, normal chase.
    if (tid == 0) {
        const int p0 = s_ptr0;
        o[SS - 1] = (float)p0;
        int ptr = p0;
        for (int k = SS - 2; k >= 0; --k) {
            if (k > last_pos)       ptr = 0;
            else if (k == last_pos) ptr = p0;
            else                    ptr = (int)bp[k + 1][ptr];
            o[k] = (float)ptr;
        }
    }
}

extern "C" void kernel_launch(void* const* d_in, const int* in_sizes, int n_in,
                              void* d_out, int out_size) {
    // feats = largest buffer, transitions = smallest; the two leftovers are
    // {mask, tags}, disambiguated by content inside the kernel.
    int fi = 0, ti = 0;
    for (int i = 1; i < n_in; ++i) {
        if (in_sizes[i] > in_sizes[fi]) fi = i;
        if (in_sizes[i] < in_sizes[ti]) ti = i;
    }
    int cA = -1, cB = -1;
    for (int i = 0; i < n_in; ++i) {
        if (i == fi || i == ti) continue;
        if (cA < 0) cA = i; else if (cB < 0) cB = i;
    }
    if (cA < 0) cA = ti;
    if (cB < 0) cB = cA;

    const int nbatch = out_size / SS;          // 128
    crf_viterbi_v16<<<nbatch, NTHR>>>((const float*)d_in[fi],
                                      (const float*)d_in[ti],
                                      (const unsigned*)d_in[cA],
                                      (const unsigned*)d_in[cB],
                                      (float*)d_out);
}

// round 17
// speedup vs baseline: 1.5320x; 1.1123x over previous
#include <cuda_runtime.h>

// CRF Viterbi decode: B=128, S=512, T=64.
// One CTA per batch, 128 threads. Warp w owns tags 16w..16w+15;
// lanes 0-15 = predecessor seg [0,32), lanes 16-31 = seg [32,64).
// ONE __syncthreads per step; cross-segment combine via __shfl_xor(16).
// R12 core (packed add.rn.f32x2, chains seeded with candidate 0, unmasked
// bp, masking in backtrack) + BLOCK-PARALLEL BACKTRACK: 32-step block
// composition maps built in parallel, serial chase only over block
// boundaries, interiors re-chased in parallel.
// Bit-exact with reference: v = (f + trans[i][j]) + part[i];
// first-occurrence argmax (fmax value chains, pred-select indices,
// ascending strict-> combines, seg0 wins ties). Output float32.

#define SS 512
#define TT 64
#define START_TAG 62
#define STOP_TAG 63
#define NTHR 128

typedef unsigned long long ull;

__device__ __forceinline__ ull addx2(ull a, ull b) {
    ull r;
    asm("add.rn.f32x2 %0, %1, %2;" : "=l"(r) : "l"(a), "l"(b));
    return r;
}
__device__ __forceinline__ ull packx2(float lo, float hi) {
    ull r;
    asm("mov.b64 %0, {%1, %2};" : "=l"(r) : "f"(lo), "f"(hi));
    return r;
}
__device__ __forceinline__ void unpackx2(ull v, float& lo, float& hi) {
    asm("mov.b64 {%0, %1}, %2;" : "=f"(lo), "=f"(hi) : "l"(v));
}

// argmax chain over 4 packed pairs (8 candidates), seeded with element 0.
// Indices BASE..BASE+7; strict > keeps earliest on ties.
#define CHAIN8(CVAL, CIDX, VV, BASE) do {                                    \
    float lo_, hi_;                                                          \
    unpackx2((VV)[0], lo_, hi_);                                             \
    CVAL = lo_; CIDX = (BASE);                                               \
    CIDX = (hi_ > CVAL) ? (BASE) + 1 : CIDX;  CVAL = fmaxf(CVAL, hi_);       \
    _Pragma("unroll")                                                        \
    for (int q_ = 1; q_ < 4; ++q_) {                                         \
        unpackx2((VV)[q_], lo_, hi_);                                        \
        CIDX = (lo_ > CVAL) ? (BASE) + 2*q_     : CIDX;                      \
        CVAL = fmaxf(CVAL, lo_);                                             \
        CIDX = (hi_ > CVAL) ? (BASE) + 2*q_ + 1 : CIDX;                      \
        CVAL = fmaxf(CVAL, hi_);                                             \
    }                                                                        \
} while (0)

__global__ __launch_bounds__(NTHR, 1)
void crf_viterbi_v17(const float* __restrict__ feats,
                     const float* __restrict__ trans,
                     const unsigned* __restrict__ candA,
                     const unsigned* __restrict__ candB,
                     float* __restrict__ out)
{
    __shared__ __align__(16) float part[2][TT];
    __shared__ float lastp[TT];
    __shared__ unsigned char bp[SS][TT];   // bp[t][j], t>=1, UNMASKED
    __shared__ unsigned char blkmap[16][TT];
    __shared__ int s_bnd[17];
    __shared__ int s_len, s_ptr0, s_clsA, s_clsB, s_ckhi;

    const int tid  = threadIdx.x;
    const int b    = blockIdx.x;
    const int warp = tid >> 5;
    const int lane = tid & 31;
    const int tag  = (warp << 4) | (lane & 15);
    const int seg  = lane >> 4;          // 0 or 1
    const int i0   = seg << 5;           // predecessor range [i0, i0+32)

    float* o = out + b * SS;

    // ---- transitions rows i0..i0+31 of column `tag`, packed in pairs
    ull trp[16];
#pragma unroll
    for (int u = 0; u < 16; ++u)
        trp[u] = packx2(trans[(i0 + 2*u) * TT + tag],
                        trans[(i0 + 2*u + 1) * TT + tag]);

    // ---- identify mask buffer + encoding by content ----------------------
    // bit0: words in {0,1} -> i32; bit1: {0,0x3F800000} -> f32;
    // bit2: bytes in {0,1} -> u8;  bit3: halves in {0,0x3F80} -> bf16
    if (tid == 0) { s_len = 0; s_clsA = 0xF; s_clsB = 0xF; }
    __syncthreads();
    {
        int fa = 0xF, fbc = 0xF;
        for (int s = tid; s < 512; s += NTHR) {
            unsigned w = candA[s];
            if (w > 1u) fa &= ~1;
            if (w != 0u && w != 0x3F800000u) fa &= ~2;
            if (w & 0xFEFEFEFEu) fa &= ~4;
            { unsigned hi = w >> 16, lo = w & 0xFFFFu;
              if (!((hi==0u||hi==0x3F80u) && (lo==0u||lo==0x3F80u))) fa &= ~8; }
            w = candB[s];
            if (w > 1u) fbc &= ~1;
            if (w != 0u && w != 0x3F800000u) fbc &= ~2;
            if (w & 0xFEFEFEFEu) fbc &= ~4;
            { unsigned hi = w >> 16, lo = w & 0xFFFFu;
              if (!((hi==0u||hi==0x3F80u) && (lo==0u||lo==0x3F80u))) fbc &= ~8; }
        }
        atomicAnd(&s_clsA, fa);
        atomicAnd(&s_clsB, fbc);
    }
    __syncthreads();
    const unsigned* maskw = s_clsA ? candA : candB;
    const int cls = s_clsA ? s_clsA : (s_clsB ? s_clsB : 1);

    // ---- sequence length = nonzero count in mask row b --------------------
    {
        int lsum = 0;
        if (cls & 3) {
            const unsigned* m = maskw + b * SS;
            for (int s = tid; s < SS; s += NTHR) lsum += (m[s] != 0u);
        } else if (cls & 4) {
            const unsigned char* m = (const unsigned char*)maskw + b * SS;
            for (int s = tid; s < SS; s += NTHR) lsum += (m[s] != 0);
        } else {
            const unsigned short* m = (const unsigned short*)maskw + b * SS;
            for (int s = tid; s < SS; s += NTHR) lsum += (m[s] != 0);
        }
        atomicAdd(&s_len, lsum);
    }

    // ---- part0 = feats[b,0,:] + transitions[START_TAG,:] ------------------
    const float* fb = feats + b * SS * TT;
    if (seg == 1) {                        // START row 62 = seg1, pair 15 lo
        float t62, t63;
        unpackx2(trp[15], t62, t63);
        float p0v = fb[tag] + t62;
        part[0][tag] = p0v;
        lastp[tag]   = p0v;                // correct when last_pos == 0
    }
    __syncthreads();
    int len = s_len;
    if (len < 1)  len = 1;
    if (len > SS) len = SS;
    const int last_pos = len - 1;

    // ---- ftr (packed) for t = 1, prefetch feat for t = 2 -------------------
    ull ftr[16];
    {
        float f1 = fb[TT + tag];
        ull fp = packx2(f1, f1);
#pragma unroll
        for (int u = 0; u < 16; ++u) ftr[u] = addx2(fp, trp[u]);
    }
    float fnext = fb[2 * TT + tag];

    // ---- forward recurrence: ONE barrier per step ---------------------------
    int buf = 0;
#pragma unroll 1
    for (int t = 1; t < SS; ++t) {
        // packed partition pairs for this segment (LDS.128)
        ull pvp[16];
        {
            const longlong2* p2 = (const longlong2*)(&part[buf][i0]);
#pragma unroll
            for (int q = 0; q < 8; ++q) {
                longlong2 w = p2[q];
                pvp[2*q]   = (ull)w.x;
                pvp[2*q+1] = (ull)w.y;
            }
        }

        // packed candidate values: v = ftr + pv (exact (f+tr)+p association)
        ull vv[16];
#pragma unroll
        for (int q = 0; q < 16; ++q) vv[q] = addx2(ftr[q], pvp[q]);

        float c0, c1, c2, c3; int d0, d1, d2, d3;
        CHAIN8(c0, d0, vv + 0,  0);
        CHAIN8(c1, d1, vv + 4,  8);
        CHAIN8(c2, d2, vv + 8,  16);
        CHAIN8(c3, d3, vv + 12, 24);

        // ascending combine; strict > keeps the earliest index on ties
        if (c1 > c0) { c0 = c1; d0 = d1; }
        if (c3 > c2) { c2 = c3; d2 = d3; }
        if (c2 > c0) { c0 = c2; d0 = d2; }
        float bg = c0;
        int   ag = i0 + d0;

        // cross-segment combine inside the warp (lanes l <-> l^16)
        float bo = __shfl_xor_sync(0xffffffffu, bg, 16);
        int   ao = __shfl_xor_sync(0xffffffffu, ag, 16);

        if (seg == 0) {
            float best = bg;  int arg = ag;      // seg0 wins ties
            if (bo > best) { best = bo; arg = ao; }
            part[buf ^ 1][tag] = best;
            bp[t][tag] = (unsigned char)arg;     // unmasked; masked in backtrack
            if (t == last_pos) lastp[tag] = best;
        }

        // build packed ftr for step t+1 BEFORE the barrier
        {
            float f = fnext;
            if (t + 2 < SS) fnext = fb[(t + 2) * TT + tag];
            ull fp = packx2(f, f);
#pragma unroll
            for (int u = 0; u < 16; ++u) ftr[u] = addx2(fp, trp[u]);
        }

        buf ^= 1;
        __syncthreads();
    }

    // ---- pointer0 = argmax_i( lastp[i] + trans[i][STOP_TAG] ) --------------
    {
        ull vv[16];
        const longlong2* p2 = (const longlong2*)(&lastp[i0]);
#pragma unroll
        for (int q = 0; q < 8; ++q) {
            longlong2 w = p2[q];
            vv[2*q]   = addx2(trp[2*q],   (ull)w.x);
            vv[2*q+1] = addx2(trp[2*q+1], (ull)w.y);
        }
        float c0, c1, c2, c3; int d0, d1, d2, d3;
        CHAIN8(c0, d0, vv + 0,  0);
        CHAIN8(c1, d1, vv + 4,  8);
        CHAIN8(c2, d2, vv + 8,  16);
        CHAIN8(c3, d3, vv + 12, 24);
        if (c1 > c0) { c0 = c1; d0 = d1; }
        if (c3 > c2) { c2 = c3; d2 = d3; }
        if (c2 > c0) { c0 = c2; d0 = d2; }
        float bg = c0;
        int   ag = i0 + d0;

        // only threads with tag == STOP_TAG hold trans[i][STOP_TAG]; the shfl
        // pairs lanes 15/31 of warp 3, both of which have tag 63.
        float bo = __shfl_xor_sync(0xffffffffu, bg, 16);
        int   ao = __shfl_xor_sync(0xffffffffu, ag, 16);
        if (seg == 0 && tag == STOP_TAG) {
            int arg = ag;
            if (bo > bg) arg = ao;
            s_ptr0 = arg;
        }
        __syncthreads();
    }

    // ---- block-parallel backtrack --------------------------------------------
    // Chain: c[last_pos] = p0; c[k] = bp[k+1][c[k+1]] for k < last_pos.
    // Outputs: o[SS-1] = p0; o[k] = 0 for last_pos < k < SS-1; o[k] = c[k] else.
    const int M   = last_pos >> 5;   // number of full 32-blocks below khi (>=3)
    const int khi = M << 5;

    // phase 0: serial chase from last_pos down to khi (<=31 deps) + tail zeros
    if (tid == 0) {
        const int p0 = s_ptr0;
        o[SS - 1] = (float)p0;
        int x = p0;
        o[last_pos] = (float)x;
        for (int k = last_pos - 1; k >= khi; --k) {
            x = (int)bp[k + 1][x];
            o[k] = (float)x;
        }
        s_ckhi = x;                          // == c[khi]
    }
    for (int k = last_pos + 1 + tid; k < SS - 1; k += NTHR) o[k] = 0.0f;
    __syncthreads();

    // phase 1: per-block composition maps (block m covers k in [32m, 32m+32))
    // blkmap[m][j] = chain value at 32m given c[32(m+1)] == j.
    for (int idx = tid; idx < (M << 6); idx += NTHR) {
        int m = idx >> 6, j = idx & 63;
        int x = j;
        int kend = m << 5;
#pragma unroll 4
        for (int k = kend + 31; k >= kend; --k)
            x = (int)bp[k + 1][x];
        blkmap[m][j] = (unsigned char)x;
    }
    __syncthreads();

    // phase 2: serial chase over block boundaries (<=15 deps)
    if (tid == 0) {
        int x = s_ckhi;
        s_bnd[M] = x;
        for (int m = M - 1; m >= 0; --m) {
            x = (int)blkmap[m][x];
            s_bnd[m] = x;
        }
    }
    __syncthreads();

    // phase 3: re-chase block interiors in parallel (32 deps each)
    if (tid < M) {
        int m = tid;
        int x = s_bnd[m + 1];
        int kend = m << 5;
#pragma unroll 4
        for (int k = kend + 31; k >= kend; --k) {
            x = (int)bp[k + 1][x];
            o[k] = (float)x;
        }
    }
}

extern "C" void kernel_launch(void* const* d_in, const int* in_sizes, int n_in,
                              void* d_out, int out_size) {
    // feats = largest buffer, transitions = smallest; the two leftovers are
    // {mask, tags}, disambiguated by content inside the kernel.
    int fi = 0, ti = 0;
    for (int i = 1; i < n_in; ++i) {
        if (in_sizes[i] > in_sizes[fi]) fi = i;
        if (in_sizes[i] < in_sizes[ti]) ti = i;
    }
    int cA = -1, cB = -1;
    for (int i = 0; i < n_in; ++i) {
        if (i == fi || i == ti) continue;
        if (cA < 0) cA = i; else if (cB < 0) cB = i;
    }
    if (cA < 0) cA = ti;
    if (cB < 0) cB = cA;

    const int nbatch = out_size / SS;          // 128
    crf_viterbi_v17<<<nbatch, NTHR>>>((const float*)d_in[fi],
                                      (const float*)d_in[ti],
                                      (const unsigned*)d_in[cA],
                                      (const unsigned*)d_in[cB],
                                      (float*)d_out);
}